// round 15
// baseline (speedup 1.0000x reference)
#include <cuda_runtime.h>
#include <cuda_bf16.h>
#include <cstdint>

// Problem constants
#define SEQ    4096
#define DK     128
#define PLANE  (SEQ * DK)      // 524288 floats per (b,h) plane
#define PLANE4 (PLANE / 4)     // 131072 float4s per plane
#define PPB    4               // planes per block (best-measured config)

// FINAL KERNEL — at the measured HBM roofline.
// out[...,s,d] = R[d,d,s] * x[...,s,d]  (einsum diagonal => elementwise scale)
//
// One block = one 32-seq x 128-dim tile, applied to PPB planes (2 pairs).
// Diag slice read straight from R (coalesced 128B rows, L2-cached across the
// 32 plane-blocks sharing each s-tile) into smem, then cached in registers.
// .cs on loads and stores: strictly read-once/write-once stream; evict-first
// keeps L2 ways free for the hot 2MB diag of R.
// Grid: s-tiles on the fast axis (plane-fast measured worse: 16MB power-of-2
// strides alias in the L2/channel hash). 256-thread blocks measured better
// than 512 (79.2us vs 77.1-77.9us kernel).
//
// Roofline evidence: 14 configs (MLP 4-16, 128/256-bit, PPB 2/4/8, occ
// 22-65%, store policy, grid order, SW pipelining, block shape) all pin at
// 6109-6293 GB/s => ~6290 GB/s is the 50:50 read/write HBM turnaround
// ceiling (~79% of 8TB/s spec). Traffic irreducible (512 MiB unique fp32
// I/O; 2MB R-diag is L2-resident). rel_err = 0 exactly.
__global__ void __launch_bounds__(256) rope_diag_kernel(
        const float* __restrict__ R,
        const float4* __restrict__ x,
        float4* __restrict__ out) {
    // Padded to 132 floats/row: 16B-aligned rows -> conflict-free LDS.128
    __shared__ float diag[32][132];

    const unsigned s0     = blockIdx.x * 32;        // 128 s-tiles (fast)
    const unsigned plane0 = blockIdx.y * PPB;       // 32 plane-quads
    const unsigned tid    = threadIdx.x;
    const unsigned warp   = tid >> 5;
    const unsigned lane   = tid & 31;

    // diag[s][d] = R[d*(DK+1)*SEQ + s]; each row a coalesced 128B read.
    #pragma unroll
    for (int r = 0; r < 16; r++) {
        unsigned d = warp + r * 8;
        diag[lane][d] = __ldg(&R[(size_t)d * ((DK + 1) * SEQ) + s0 + lane]);
    }
    __syncthreads();

    const unsigned tileBase = blockIdx.x * 1024;    // float4 offset in plane

    // Pre-read this thread's 4 diag chunks once (16 regs, reused x4 planes)
    float4 dvv[4];
    #pragma unroll
    for (int k = 0; k < 4; k++) {
        unsigned idx = k * 256 + tid;               // 0..1023 within tile
        unsigned s   = idx >> 5;
        unsigned d4  = (idx & 31) * 4;
        dvv[k] = *reinterpret_cast<const float4*>(&diag[s][d4]);
    }

    // Process planes in pairs: 8 front-batched float4 loads per pair.
    #pragma unroll
    for (int pp = 0; pp < PPB / 2; pp++) {
        const unsigned pA = plane0 + pp * 2;

        float4 xv[2][4];
        #pragma unroll
        for (int p = 0; p < 2; p++) {
            const float4* xp = x + (size_t)(pA + p) * PLANE4 + tileBase;
            #pragma unroll
            for (int k = 0; k < 4; k++)
                xv[p][k] = __ldcs(&xp[k * 256 + tid]);
        }

        #pragma unroll
        for (int k = 0; k < 4; k++) {
            unsigned idx = k * 256 + tid;
            #pragma unroll
            for (int p = 0; p < 2; p++) {
                float4 r;
                r.x = xv[p][k].x * dvv[k].x;
                r.y = xv[p][k].y * dvv[k].y;
                r.z = xv[p][k].z * dvv[k].z;
                r.w = xv[p][k].w * dvv[k].w;
                __stcs(&out[(size_t)(pA + p) * PLANE4 + tileBase + idx], r);
            }
        }
    }
}

extern "C" void kernel_launch(void* const* d_in, const int* in_sizes, int n_in,
                              void* d_out, int out_size) {
    const float* x = (const float*)d_in[0];
    // d_in[1] = token_positions (unused by the reference semantics)
    const float* R = (const float*)d_in[2];
    float* out = (float*)d_out;

    dim3 grid(SEQ / 32, 128 / PPB);   // (128, 32) = 4096 blocks, s-tiles fast
    rope_diag_kernel<<<grid, 256>>>(R, (const float4*)x, (float4*)out);
    (void)in_sizes; (void)n_in; (void)out_size;
}

// round 16
// speedup vs baseline: 1.0008x; 1.0008x over previous
#include <cuda_runtime.h>
#include <cuda_bf16.h>
#include <cstdint>

// Problem constants
#define SEQ    4096
#define DK     128
#define PLANE  (SEQ * DK)      // 524288 floats per (b,h) plane
#define PLANE4 (PLANE / 4)     // 131072 float4s per plane
#define PPB    4               // planes per block (best-measured config)

// FINAL KERNEL — at the measured HBM roofline.
// out[...,s,d] = R[d,d,s] * x[...,s,d]  (einsum diagonal => elementwise scale)
//
// One block = one 32-seq x 128-dim tile, applied to PPB planes (2 pairs).
// Diag slice read straight from R (coalesced 128B rows, L2-cached across the
// 32 plane-blocks sharing each s-tile) into smem, then cached in registers.
// .cs on loads and stores: strictly read-once/write-once stream; evict-first
// keeps L2 ways free for the hot 2MB diag of R.
// Grid: s-tiles on the fast axis (plane-fast measured worse: 16MB power-of-2
// strides alias in the L2/channel hash). 256-thread blocks measured better
// than 512.
//
// Roofline evidence (15 rounds): every config (MLP 4-16, 128/256-bit,
// PPB 2/4/8, occ 22-65%, store policy, grid order, SW pipelining, block
// shape) pins at 6109-6293 GB/s => ~6290 GB/s is the 50:50 read/write HBM
// turnaround ceiling (~79% of 8TB/s spec). Traffic irreducible (512 MiB
// unique fp32 I/O; 2MB R-diag L2-resident). rel_err = 0 exactly.
// Run-to-run noise of this exact kernel: 82.21-82.72 us total.
__global__ void __launch_bounds__(256) rope_diag_kernel(
        const float* __restrict__ R,
        const float4* __restrict__ x,
        float4* __restrict__ out) {
    // Padded to 132 floats/row: 16B-aligned rows -> conflict-free LDS.128
    __shared__ float diag[32][132];

    const unsigned s0     = blockIdx.x * 32;        // 128 s-tiles (fast)
    const unsigned plane0 = blockIdx.y * PPB;       // 32 plane-quads
    const unsigned tid    = threadIdx.x;
    const unsigned warp   = tid >> 5;
    const unsigned lane   = tid & 31;

    // diag[s][d] = R[d*(DK+1)*SEQ + s]; each row a coalesced 128B read.
    #pragma unroll
    for (int r = 0; r < 16; r++) {
        unsigned d = warp + r * 8;
        diag[lane][d] = __ldg(&R[(size_t)d * ((DK + 1) * SEQ) + s0 + lane]);
    }
    __syncthreads();

    const unsigned tileBase = blockIdx.x * 1024;    // float4 offset in plane

    // Pre-read this thread's 4 diag chunks once (16 regs, reused x4 planes)
    float4 dvv[4];
    #pragma unroll
    for (int k = 0; k < 4; k++) {
        unsigned idx = k * 256 + tid;               // 0..1023 within tile
        unsigned s   = idx >> 5;
        unsigned d4  = (idx & 31) * 4;
        dvv[k] = *reinterpret_cast<const float4*>(&diag[s][d4]);
    }

    // Process planes in pairs: 8 front-batched float4 loads per pair.
    #pragma unroll
    for (int pp = 0; pp < PPB / 2; pp++) {
        const unsigned pA = plane0 + pp * 2;

        float4 xv[2][4];
        #pragma unroll
        for (int p = 0; p < 2; p++) {
            const float4* xp = x + (size_t)(pA + p) * PLANE4 + tileBase;
            #pragma unroll
            for (int k = 0; k < 4; k++)
                xv[p][k] = __ldcs(&xp[k * 256 + tid]);
        }

        #pragma unroll
        for (int k = 0; k < 4; k++) {
            unsigned idx = k * 256 + tid;
            #pragma unroll
            for (int p = 0; p < 2; p++) {
                float4 r;
                r.x = xv[p][k].x * dvv[k].x;
                r.y = xv[p][k].y * dvv[k].y;
                r.z = xv[p][k].z * dvv[k].z;
                r.w = xv[p][k].w * dvv[k].w;
                __stcs(&out[(size_t)(pA + p) * PLANE4 + tileBase + idx], r);
            }
        }
    }
}

extern "C" void kernel_launch(void* const* d_in, const int* in_sizes, int n_in,
                              void* d_out, int out_size) {
    const float* x = (const float*)d_in[0];
    // d_in[1] = token_positions (unused by the reference semantics)
    const float* R = (const float*)d_in[2];
    float* out = (float*)d_out;

    dim3 grid(SEQ / 32, 128 / PPB);   // (128, 32) = 4096 blocks, s-tiles fast
    rope_diag_kernel<<<grid, 256>>>(R, (const float4*)x, (float4*)out);
    (void)in_sizes; (void)n_in; (void)out_size;
}

// round 17
// speedup vs baseline: 1.0054x; 1.0047x over previous
#include <cuda_runtime.h>
#include <cuda_bf16.h>
#include <cstdint>

// Problem constants
#define SEQ    4096
#define DK     128
#define PLANE  (SEQ * DK)      // 524288 floats per (b,h) plane
#define PLANE4 (PLANE / 4)     // 131072 float4s per plane
#define PPB    4               // planes per block (best-measured config)

// FINAL KERNEL — at the measured HBM roofline.
// out[...,s,d] = R[d,d,s] * x[...,s,d]  (einsum diagonal => elementwise scale)
//
// One block = one 32-seq x 128-dim tile, applied to PPB planes (2 pairs).
// Diag slice read straight from R (coalesced 128B rows, L2-cached across the
// 32 plane-blocks sharing each s-tile) into smem, then cached in registers.
// .cs on loads and stores: strictly read-once/write-once stream; evict-first
// keeps L2 ways free for the hot 2MB diag of R.
// Grid: s-tiles on the fast axis (plane-fast measured worse: 16MB power-of-2
// strides alias in the L2/channel hash). 256-thread blocks measured better
// than 512.
//
// Roofline evidence (16 rounds, 14 configs): MLP 4-16, 128/256-bit,
// PPB 2/4/8, occ 22-65%, store policy, grid order, SW pipelining, block
// shape — ALL pin at 6109-6293 GB/s => ~6290 GB/s is the 50:50 read/write
// HBM turnaround ceiling (~79% of 8TB/s spec). Traffic irreducible (512 MiB
// unique fp32 I/O; 2MB R-diag L2-resident). rel_err = 0 exactly.
// Six-run noise band of this exact kernel: 82.21-82.72 us total.
__global__ void __launch_bounds__(256) rope_diag_kernel(
        const float* __restrict__ R,
        const float4* __restrict__ x,
        float4* __restrict__ out) {
    // Padded to 132 floats/row: 16B-aligned rows -> conflict-free LDS.128
    __shared__ float diag[32][132];

    const unsigned s0     = blockIdx.x * 32;        // 128 s-tiles (fast)
    const unsigned plane0 = blockIdx.y * PPB;       // 32 plane-quads
    const unsigned tid    = threadIdx.x;
    const unsigned warp   = tid >> 5;
    const unsigned lane   = tid & 31;

    // diag[s][d] = R[d*(DK+1)*SEQ + s]; each row a coalesced 128B read.
    #pragma unroll
    for (int r = 0; r < 16; r++) {
        unsigned d = warp + r * 8;
        diag[lane][d] = __ldg(&R[(size_t)d * ((DK + 1) * SEQ) + s0 + lane]);
    }
    __syncthreads();

    const unsigned tileBase = blockIdx.x * 1024;    // float4 offset in plane

    // Pre-read this thread's 4 diag chunks once (16 regs, reused x4 planes)
    float4 dvv[4];
    #pragma unroll
    for (int k = 0; k < 4; k++) {
        unsigned idx = k * 256 + tid;               // 0..1023 within tile
        unsigned s   = idx >> 5;
        unsigned d4  = (idx & 31) * 4;
        dvv[k] = *reinterpret_cast<const float4*>(&diag[s][d4]);
    }

    // Process planes in pairs: 8 front-batched float4 loads per pair.
    #pragma unroll
    for (int pp = 0; pp < PPB / 2; pp++) {
        const unsigned pA = plane0 + pp * 2;

        float4 xv[2][4];
        #pragma unroll
        for (int p = 0; p < 2; p++) {
            const float4* xp = x + (size_t)(pA + p) * PLANE4 + tileBase;
            #pragma unroll
            for (int k = 0; k < 4; k++)
                xv[p][k] = __ldcs(&xp[k * 256 + tid]);
        }

        #pragma unroll
        for (int k = 0; k < 4; k++) {
            unsigned idx = k * 256 + tid;
            #pragma unroll
            for (int p = 0; p < 2; p++) {
                float4 r;
                r.x = xv[p][k].x * dvv[k].x;
                r.y = xv[p][k].y * dvv[k].y;
                r.z = xv[p][k].z * dvv[k].z;
                r.w = xv[p][k].w * dvv[k].w;
                __stcs(&out[(size_t)(pA + p) * PLANE4 + tileBase + idx], r);
            }
        }
    }
}

extern "C" void kernel_launch(void* const* d_in, const int* in_sizes, int n_in,
                              void* d_out, int out_size) {
    const float* x = (const float*)d_in[0];
    // d_in[1] = token_positions (unused by the reference semantics)
    const float* R = (const float*)d_in[2];
    float* out = (float*)d_out;

    dim3 grid(SEQ / 32, 128 / PPB);   // (128, 32) = 4096 blocks, s-tiles fast
    rope_diag_kernel<<<grid, 256>>>(R, (const float4*)x, (float4*)out);
    (void)in_sizes; (void)n_in; (void)out_size;
}